// round 6
// baseline (speedup 1.0000x reference)
#include <cuda_runtime.h>
#include <cstdint>
#include <cstddef>

typedef unsigned long long ull;

#define NB   256   // batch
#define NH   256   // hidden
#define NS   512   // sequence length
#define NIN  32    // input features
#define NCTA 128   // scan grid: 16 hidden-blocks x 8 batch-blocks
#define NTHR 256   // scan block

// ---------------- static device scratch (no allocation allowed) --------------
__device__ float g_xT[(size_t)NS * NIN * NB];        // x transposed: [t][i][b]
__device__ float g_h1[(size_t)NS * NH * NB];         // layer-0 outputs [t][k][b]
__device__ float g_hbuf[2 * NH * NB];                // double-buffered h [k][b]
__device__ float g_final[NH * NB];                   // final hidden [k][b]
__device__ float g_s[NB * 128];                      // projected states [b][row]
__device__ unsigned g_cnt;
__device__ volatile unsigned g_gen;

// ---------------- f32x2 helpers (B300 full-rate fp32 path) -------------------
__device__ __forceinline__ ull pack2(float w) {
    ull r; unsigned u = __float_as_uint(w);
    asm("mov.b64 %0, {%1, %1};" : "=l"(r) : "r"(u));
    return r;
}
__device__ __forceinline__ void fma2(ull& acc, ull a, ull b) {
    asm("fma.rn.f32x2 %0, %1, %2, %0;" : "+l"(acc) : "l"(a), "l"(b));
}
__device__ __forceinline__ ull add2(ull a, ull b) {
    ull d; asm("add.rn.f32x2 %0, %1, %2;" : "=l"(d) : "l"(a), "l"(b));
    return d;
}
__device__ __forceinline__ float2 u2f(ull v) {
    float2 f;
    f.x = __uint_as_float((unsigned)(v & 0xffffffffull));
    f.y = __uint_as_float((unsigned)(v >> 32));
    return f;
}
__device__ __forceinline__ float sigm(float x) { return 1.0f / (1.0f + expf(-x)); }

// ---------------- software grid barrier (all 128 CTAs resident) --------------
__device__ __forceinline__ void grid_barrier(unsigned target) {
    __threadfence();              // make this CTA's h stores visible device-wide
    __syncthreads();
    if (threadIdx.x == 0) {
        unsigned prev = atomicAdd(&g_cnt, 1u);
        if (prev == gridDim.x - 1) {
            atomicExch(&g_cnt, 0u);
            __threadfence();
            g_gen = target;       // release
        } else {
            while (g_gen != target) {}
            __threadfence();      // acquire
        }
    }
    __syncthreads();
}

__global__ void reset_bar() { g_cnt = 0u; g_gen = 0u; }

// ---------------- x transpose: [b][t][i] -> [t][i][b] ------------------------
__global__ void transpose_x(const float* __restrict__ x) {
    __shared__ float tile[32][33];
    int t    = blockIdx.x;
    int lane = threadIdx.x & 31;
    int grp  = threadIdx.x >> 5;   // 0..7
    for (int bc = 0; bc < NB; bc += 32) {
#pragma unroll
        for (int q = 0; q < 4; ++q) {
            int bsub = q * 8 + grp;
            tile[bsub][lane] = x[((size_t)(bc + bsub) * NS + t) * NIN + lane];
        }
        __syncthreads();
#pragma unroll
        for (int q = 0; q < 4; ++q) {
            int ii = q * 8 + grp;
            g_xT[((size_t)t * NIN + ii) * NB + bc + lane] = tile[lane][ii];
        }
        __syncthreads();
    }
}

// ---------------- fused GRU scan (input projection + recurrence) -------------
// Per step: gates[3][16j][32b] = Wih.in[t] + Whh.h(t-1) for this CTA's tile,
// then the GRU pointwise update. Thread tile: 3 gates x 4 batch (2 f32x2 accums
// per gate), 2-way K split across the 256 threads with an smem reduction.
// W_hh lives in smem PRE-DUPLICATED as (w,w) 64-bit pairs: the hot recurrent
// loop is then 3 LDS.64(w) + 2 LDS.64(h) + 6 FFMA2 per k -> FMA-pipe-bound.
template <int LAYER>
__global__ void __launch_bounds__(NTHR, 1)
gru_scan(const float* __restrict__ Wih, const float* __restrict__ Whh,
         const float* __restrict__ bih, const float* __restrict__ bhh)
{
    constexpr int KIN = (LAYER == 0) ? NIN : NH;
    extern __shared__ char smraw[];
    ull*   sWhh2 = reinterpret_cast<ull*>(smraw);            // [256*48] ull (dup'd)
    float* sWih  = reinterpret_cast<float*>(sWhh2 + NH*48);  // [KIN*48]
    float* sIn   = sWih + KIN * 48;                          // [KIN][32]
    float* sH    = sIn + KIN * 32;                           // [256][32]
    float* sRed  = sH + NH * 32;                             // [128][24] reduction

    const int tid = threadIdx.x;
    const int kg  = tid >> 7;               // K half: 0 or 1
    const int t7  = tid & 127;
    const int j   = t7 >> 3;                // 0..15 hidden within block
    const int bq  = t7 & 7;                 // 0..7 batch quad (4 batches)
    const int jb  = blockIdx.x & 15;
    const int bb  = blockIdx.x >> 4;

    const float* inbase = (LAYER == 0) ? g_xT : g_h1;

    // load weight slices into smem, k-major
    for (int e = tid; e < NH * 48; e += NTHR) {
        int k = e / 48, r = e - k * 48;
        int row = (r >> 4) * NH + jb * 16 + (r & 15);
        sWhh2[e] = pack2(Whh[row * NH + k]);
    }
    for (int e = tid; e < KIN * 48; e += NTHR) {
        int k = e / 48, r = e - k * 48;
        int row = (r >> 4) * NH + jb * 16 + (r & 15);
        sWih[e] = Wih[row * KIN + k];
    }
    float bihv[3], bhhv[3];
#pragma unroll
    for (int g = 0; g < 3; ++g) {
        int row = g * NH + jb * 16 + j;
        bihv[g] = bih[row];
        bhhv[g] = bhh[row];
    }
    // preload input tile for t=0
    {
        const float* ip = inbase + bb * 32;
        for (int e = tid; e < KIN * 32; e += NTHR)
            sIn[e] = ip[(size_t)(e >> 5) * NB + (e & 31)];
    }
    __syncthreads();

    for (int t = 0; t < NS; ++t) {
        if (t > 0) {
            // h exchange through L2 (L1 is incoherent across SMs)
            const float* hp = g_hbuf + ((t - 1) & 1) * (NH * NB) + bb * 32;
            for (int e = tid; e < NH * 32; e += NTHR)
                sH[e] = __ldcg(hp + (e >> 5) * NB + (e & 31));
        }
        __syncthreads();

        ull ax[3][2] = {{0ull,0ull},{0ull,0ull},{0ull,0ull}};
        ull ah[3][2] = {{0ull,0ull},{0ull,0ull},{0ull,0ull}};

        {   // fused input projection
            const int kh = KIN >> 1;
            const int kb = kg * kh;
#pragma unroll 4
            for (int kk = 0; kk < kh; ++kk) {
                int k = kb + kk;
                const float* wr = sWih + k * 48 + j;
                ull i0 = *reinterpret_cast<const ull*>(sIn + (k << 5) + (bq << 2));
                ull i1 = *reinterpret_cast<const ull*>(sIn + (k << 5) + (bq << 2) + 2);
#pragma unroll
                for (int g = 0; g < 3; ++g) {
                    ull w2 = pack2(wr[g << 4]);
                    fma2(ax[g][0], w2, i0);
                    fma2(ax[g][1], w2, i1);
                }
            }
        }
        if (t > 0) {   // recurrent part (hot loop: weights already duplicated)
            const int kb = kg * 128;
#pragma unroll 4
            for (int kk = 0; kk < 128; ++kk) {
                int k = kb + kk;
                const ull* wr = sWhh2 + k * 48 + j;
                ull h0 = *reinterpret_cast<const ull*>(sH + (k << 5) + (bq << 2));
                ull h1 = *reinterpret_cast<const ull*>(sH + (k << 5) + (bq << 2) + 2);
#pragma unroll
                for (int g = 0; g < 3; ++g) {
                    ull w2 = wr[g << 4];
                    fma2(ah[g][0], w2, h0);
                    fma2(ah[g][1], w2, h1);
                }
            }
        }

        if (kg == 1) {  // publish upper-K partials
            ull* rp = reinterpret_cast<ull*>(sRed) + t7 * 12;
            int q = 0;
#pragma unroll
            for (int g = 0; g < 3; ++g) { rp[q++] = ax[g][0]; rp[q++] = ax[g][1]; }
#pragma unroll
            for (int g = 0; g < 3; ++g) { rp[q++] = ah[g][0]; rp[q++] = ah[g][1]; }
        }
        __syncthreads();   // partials visible; sIn/sH reads for step t done

        // prefetch next step's input tile (independent of h) during epilogue
        if (t + 1 < NS) {
            const float* ip = inbase + (size_t)(t + 1) * KIN * NB + bb * 32;
            for (int e = tid; e < KIN * 32; e += NTHR)
                sIn[e] = ip[(size_t)(e >> 5) * NB + (e & 31)];
        }

        if (kg == 0) {  // reduce + GRU update + store
            const ull* rp = reinterpret_cast<const ull*>(sRed) + t7 * 12;
            int q = 0;
#pragma unroll
            for (int g = 0; g < 3; ++g) {
                ax[g][0] = add2(ax[g][0], rp[q]); ++q;
                ax[g][1] = add2(ax[g][1], rp[q]); ++q;
            }
#pragma unroll
            for (int g = 0; g < 3; ++g) {
                ah[g][0] = add2(ah[g][0], rp[q]); ++q;
                ah[g][1] = add2(ah[g][1], rp[q]); ++q;
            }

            const int jg   = jb * 16 + j;            // global hidden index
            const int bcol = bb * 32 + (bq << 2);    // global batch index
            float hprev[4] = {0.f, 0.f, 0.f, 0.f};
            if (t > 0) {
                float4 hv = *reinterpret_cast<const float4*>(sH + jg * 32 + (bq << 2));
                hprev[0] = hv.x; hprev[1] = hv.y; hprev[2] = hv.z; hprev[3] = hv.w;
            }
            float o[4];
#pragma unroll
            for (int p = 0; p < 2; ++p) {
                float2 xr = u2f(ax[0][p]), xz = u2f(ax[1][p]), xn = u2f(ax[2][p]);
                float2 hr = u2f(ah[0][p]), hz = u2f(ah[1][p]), hn = u2f(ah[2][p]);
#pragma unroll
                for (int l = 0; l < 2; ++l) {
                    float vxr = (l ? xr.y : xr.x) + bihv[0];
                    float vxz = (l ? xz.y : xz.x) + bihv[1];
                    float vxn = (l ? xn.y : xn.x) + bihv[2];
                    float vhr = (l ? hr.y : hr.x) + bhhv[0];
                    float vhz = (l ? hz.y : hz.x) + bhhv[1];
                    float vhn = (l ? hn.y : hn.x) + bhhv[2];
                    float rr = sigm(vxr + vhr);
                    float zz = sigm(vxz + vhz);
                    float nn = tanhf(vxn + rr * vhn);  // b_hh_n inside r*(.), per GRU spec
                    o[p * 2 + l] = (1.0f - zz) * nn + zz * hprev[p * 2 + l];
                }
            }
            float4 ov = make_float4(o[0], o[1], o[2], o[3]);
            *reinterpret_cast<float4*>(g_hbuf + (t & 1) * (NH * NB) + jg * NB + bcol) = ov;
            if (LAYER == 0)
                *reinterpret_cast<float4*>(g_h1 + ((size_t)t * NH + jg) * NB + bcol) = ov;
            if (LAYER == 1 && t == NS - 1)
                *reinterpret_cast<float4*>(g_final + jg * NB + bcol) = ov;
        }

        if (t < NS - 1) grid_barrier((unsigned)(t + 1));
    }
}

// ---------------- projection: s = W_proj . final_h + b_proj ------------------
__global__ void proj_kernel(const float* __restrict__ Wp, const float* __restrict__ bp) {
    int row = blockIdx.x;          // 0..127
    __shared__ float w[NH];
    for (int k = threadIdx.x; k < NH; k += blockDim.x) w[k] = Wp[row * NH + k];
    __syncthreads();
    int b = threadIdx.x;           // 0..255
    float acc = bp[row];
#pragma unroll 8
    for (int k = 0; k < NH; ++k) acc += w[k] * g_final[k * NB + b];
    g_s[b * 128 + row] = acc;
}

// ---------------- exponential-smoothing forecast recurrence ------------------
__global__ void forecast_kernel(const float* __restrict__ C,
                                const float* __restrict__ rld, const float* __restrict__ rtd,
                                const float* __restrict__ rg,  const float* __restrict__ om,
                                float* __restrict__ out)
{
    int gid = blockIdx.x * blockDim.x + threadIdx.x;
    if (gid >= NB * 32) return;
    int d = gid & 31, b = gid >> 5;
    float a_l = sigm(rld[d]) * 0.15f + 0.85f;
    float a_t = sigm(rtd[d]) * 0.25f + 0.70f;
    float gg  = sigm(rg[d])  * 0.20f + 0.80f;
    float cs = cosf(om[d]), sn = sinf(om[d]);
    float r00 = gg * cs, r01 = -gg * sn, r10 = gg * sn, r11 = gg * cs;
    float C0 = C[d * 4 + 0], C1 = C[d * 4 + 1], C2 = C[d * 4 + 2], C3 = C[d * 4 + 3];
    float s0 = g_s[b * 128 + d * 4 + 0];
    float s1 = g_s[b * 128 + d * 4 + 1];
    float s2 = g_s[b * 128 + d * 4 + 2];
    float s3 = g_s[b * 128 + d * 4 + 3];
    float* ob = out + (size_t)b * 96 * 32 + d;
#pragma unroll 4
    for (int t = 0; t < 96; ++t) {
        float ns0 = s0 * a_l;
        float ns1 = s1 * a_t;
        float ns2 = s2 * r00 + s3 * r10;
        float ns3 = s2 * r01 + s3 * r11;
        ob[t * 32] = C0 * ns0 + C1 * ns1 + C2 * ns2 + C3 * ns3;
        s0 = ns0; s1 = ns1; s2 = ns2; s3 = ns3;
    }
}

// ---------------- launch ------------------------------------------------------
extern "C" void kernel_launch(void* const* d_in, const int* in_sizes, int n_in,
                              void* d_out, int out_size)
{
    const float* x      = (const float*)d_in[0];
    const float* Wih0   = (const float*)d_in[1];
    const float* Whh0   = (const float*)d_in[2];
    const float* bih0   = (const float*)d_in[3];
    const float* bhh0   = (const float*)d_in[4];
    const float* Wih1   = (const float*)d_in[5];
    const float* Whh1   = (const float*)d_in[6];
    const float* bih1   = (const float*)d_in[7];
    const float* bhh1   = (const float*)d_in[8];
    const float* Wp     = (const float*)d_in[9];
    const float* bp     = (const float*)d_in[10];
    const float* C      = (const float*)d_in[11];
    const float* rld    = (const float*)d_in[12];
    const float* rtd    = (const float*)d_in[13];
    const float* rg     = (const float*)d_in[14];
    const float* om     = (const float*)d_in[15];
    float* out = (float*)d_out;

    // smem bytes: Whh dup'd (8B/elem) + Wih (4B) + in tile + h tile + reduction
    const int smem0 = NH * 48 * 8 + NIN * 48 * 4 + NIN * 32 * 4 + NH * 32 * 4 + 128 * 24 * 4;
    const int smem1 = NH * 48 * 8 + NH  * 48 * 4 + NH  * 32 * 4 + NH * 32 * 4 + 128 * 24 * 4;
    // idempotent, host-side only (not captured); called every time per harness rules
    cudaFuncSetAttribute(gru_scan<0>, cudaFuncAttributeMaxDynamicSharedMemorySize, smem0);
    cudaFuncSetAttribute(gru_scan<1>, cudaFuncAttributeMaxDynamicSharedMemorySize, smem1);

    transpose_x<<<NS, 256>>>(x);
    reset_bar<<<1, 1>>>();
    gru_scan<0><<<NCTA, NTHR, smem0>>>(Wih0, Whh0, bih0, bhh0);
    reset_bar<<<1, 1>>>();
    gru_scan<1><<<NCTA, NTHR, smem1>>>(Wih1, Whh1, bih1, bhh1);
    proj_kernel<<<128, 256>>>(Wp, bp);
    forecast_kernel<<<32, 256>>>(C, rld, rtd, rg, om, out);
}

// round 8
// speedup vs baseline: 1.1864x; 1.1864x over previous
#include <cuda_runtime.h>
#include <cstdint>
#include <cstddef>

typedef unsigned long long ull;

#define NB   256   // batch
#define NH   256   // hidden
#define NS   512   // sequence length
#define NIN  32    // input features
#define NCTA 128   // 16 hidden-blocks x 8 batch-blocks
#define NTHR 512   // 16 warps: 4-way K split x 128 (16j x 8bq)

// ---------------- static device scratch --------------------------------------
__device__ float g_xT[(size_t)NS * NIN * NB];   // x transposed [t][i][b]
__device__ float g_h1[(size_t)NS * NH * NB];    // layer-0 outputs [t][k][b]
__device__ float g_hbuf[2 * NH * NB];           // double-buffered h [k][b]
__device__ float g_final[NH * NB];              // final hidden [k][b]
__device__ float g_s[128 * NB];                 // projected states [row][b]
__device__ unsigned g_cnt;                      // barrier arrivals (0 at kernel boundaries)
__device__ volatile unsigned g_gen;             // barrier generation (equality-released)

// ---------------- f32x2 helpers (B300 full-rate fp32 path) -------------------
__device__ __forceinline__ ull pack2(float w) {
    ull r; unsigned u = __float_as_uint(w);
    asm("mov.b64 %0, {%1, %1};" : "=l"(r) : "r"(u));
    return r;
}
__device__ __forceinline__ void fma2(ull& acc, ull a, ull b) {
    asm("fma.rn.f32x2 %0, %1, %2, %0;" : "+l"(acc) : "l"(a), "l"(b));
}
__device__ __forceinline__ ull add2(ull a, ull b) {
    ull d; asm("add.rn.f32x2 %0, %1, %2;" : "=l"(d) : "l"(a), "l"(b));
    return d;
}
__device__ __forceinline__ float2 u2f(ull v) {
    float2 f;
    f.x = __uint_as_float((unsigned)(v & 0xffffffffull));
    f.y = __uint_as_float((unsigned)(v >> 32));
    return f;
}
__device__ __forceinline__ float sigm(float x) { return 1.0f / (1.0f + expf(-x)); }

// ---------------- software grid barrier (128 resident CTAs) ------------------
// Equality-compared target; release pre-resets g_cnt and overwrites g_gen, so
// no host-side reset is needed across launches or graph replays (successive
// first-targets always differ from the leftover g_gen value).
__device__ __forceinline__ void grid_barrier(unsigned target) {
    __threadfence();
    __syncthreads();
    if (threadIdx.x == 0) {
        unsigned prev = atomicAdd(&g_cnt, 1u);
        if (prev == gridDim.x - 1) {
            atomicExch(&g_cnt, 0u);
            __threadfence();
            g_gen = target;            // release
        } else {
            while (g_gen != target) { __nanosleep(40); }
            __threadfence();
        }
    }
    __syncthreads();
}

// ---------------- fused persistent GRU scan ----------------------------------
// LAYER 0: prologue transposes x into g_xT; writes per-step h to g_h1.
// LAYER 1: epilogue does the projection + 96-step forecast (writes d_out).
// Per step: gates = Wih.in[t] + Whh.h(t-1); thread tile 3 gates x 4 batch
// (2 f32x2 accs/gate); 4-way K split; two-wave smem reduction publishing only
// 8 ull/thread (r,z need just the x+h sum; n needs the halves apart).
template <int LAYER>
__global__ void __launch_bounds__(NTHR, 1)
gru_scan(const float* __restrict__ Wih, const float* __restrict__ Whh,
         const float* __restrict__ bih, const float* __restrict__ bhh,
         const float* __restrict__ Wp,  const float* __restrict__ bp,
         const float* __restrict__ C,
         const float* __restrict__ rld, const float* __restrict__ rtd,
         const float* __restrict__ rg,  const float* __restrict__ om,
         const float* __restrict__ x,   float* __restrict__ out)
{
    constexpr int KIN = (LAYER == 0) ? NIN : NH;
    extern __shared__ char smraw[];
    ull*   sWhh2 = reinterpret_cast<ull*>(smraw);            // [256*48] (dup'd pairs)
    float* sWih  = reinterpret_cast<float*>(sWhh2 + NH*48);  // [KIN*48]
    float* sIn   = sWih + KIN * 48;                          // [KIN][32]
    float* sH    = sIn + KIN * 32;                           // [256][32]
    ull*   bufA  = reinterpret_cast<ull*>(sH + NH * 32);     // [8][128]
    ull*   bufB  = bufA + 8 * 128;                           // [8][128]

    const int tid = threadIdx.x;
    const int kg  = tid >> 7;               // K quarter: 0..3 (warp-uniform)
    const int t7  = tid & 127;
    const int j   = t7 >> 3;                // 0..15 hidden within block
    const int bq  = t7 & 7;                 // 0..7 batch quad
    const int jb  = blockIdx.x & 15;
    const int bb  = blockIdx.x >> 4;

    if (LAYER == 0) {
        // prologue: transpose x [b][t][i] -> g_xT [t][i][b]; 4 t per CTA
        float* st = reinterpret_cast<float*>(smraw);   // [32][257] scratch
        for (int tt = 0; tt < 4; ++tt) {
            int t = blockIdx.x * 4 + tt;
            for (int e = tid; e < NB * NIN; e += NTHR) {
                int b = e >> 5, i = e & 31;
                st[i * 257 + b] = x[((size_t)b * NS + t) * NIN + i];
            }
            __syncthreads();
            for (int e = tid; e < NIN * NB; e += NTHR) {
                int i = e >> 8, b = e & 255;
                g_xT[((size_t)t * NIN + i) * NB + b] = st[i * 257 + b];
            }
            __syncthreads();
        }
        grid_barrier(700u);
    }

    // weight slices into smem, k-major; Whh pre-duplicated as (w,w) pairs
    for (int e = tid; e < NH * 48; e += NTHR) {
        int k = e / 48, r = e - k * 48;
        int row = (r >> 4) * NH + jb * 16 + (r & 15);
        sWhh2[e] = pack2(Whh[row * NH + k]);
    }
    for (int e = tid; e < KIN * 48; e += NTHR) {
        int k = e / 48, r = e - k * 48;
        int row = (r >> 4) * NH + jb * 16 + (r & 15);
        sWih[e] = Wih[row * KIN + k];
    }
    float brz0, brz1, bni, bnh;
    {
        int r0 = jb * 16 + j;
        brz0 = bih[r0] + bhh[r0];
        brz1 = bih[NH + r0] + bhh[NH + r0];
        bni  = bih[2 * NH + r0];
        bnh  = bhh[2 * NH + r0];
    }
    const float* inbase = (LAYER == 0) ? g_xT : g_h1;
    for (int e = tid; e < KIN * 32; e += NTHR)
        sIn[e] = __ldcg(inbase + (size_t)(e >> 5) * NB + bb * 32 + (e & 31));
    __syncthreads();

    for (int t = 0; t < NS; ++t) {
        if (t > 0) {
            // h exchange through L2 (L1 incoherent across SMs)
            const float* hp = g_hbuf + ((t - 1) & 1) * (NH * NB) + bb * 32;
            for (int e = tid; e < NH * 32; e += NTHR)
                sH[e] = __ldcg(hp + (e >> 5) * NB + (e & 31));
            __syncthreads();
        }

        ull ax[3][2] = {{0ull,0ull},{0ull,0ull},{0ull,0ull}};
        ull ah[3][2] = {{0ull,0ull},{0ull,0ull},{0ull,0ull}};

        {   // fused input projection (quarter of KIN per K-group)
            constexpr int kh = KIN / 4;
            const int kb = kg * kh;
#pragma unroll 8
            for (int kk = 0; kk < kh; ++kk) {
                int k = kb + kk;
                const float* wr = sWih + k * 48 + j;
                ull i0 = *reinterpret_cast<const ull*>(sIn + (k << 5) + (bq << 2));
                ull i1 = *reinterpret_cast<const ull*>(sIn + (k << 5) + (bq << 2) + 2);
#pragma unroll
                for (int g = 0; g < 3; ++g) {
                    ull w2 = pack2(wr[g << 4]);
                    fma2(ax[g][0], w2, i0);
                    fma2(ax[g][1], w2, i1);
                }
            }
        }
        if (t > 0) {   // recurrent quarter (dup'd weights -> pure LDS.64+FFMA2)
            const int kb = kg * 64;
#pragma unroll 8
            for (int kk = 0; kk < 64; ++kk) {
                int k = kb + kk;
                const ull* wr = sWhh2 + k * 48 + j;
                ull h0 = *reinterpret_cast<const ull*>(sH + (k << 5) + (bq << 2));
                ull h1 = *reinterpret_cast<const ull*>(sH + (k << 5) + (bq << 2) + 2);
#pragma unroll
                for (int g = 0; g < 3; ++g) {
                    ull w2 = wr[g << 4];
                    fma2(ah[g][0], w2, h0);
                    fma2(ah[g][1], w2, h1);
                }
            }
        }

        // local combine: r,z need x+h summed; n keeps halves separate -> 8 ull
        ull V[8];
        V[0] = add2(ax[0][0], ah[0][0]);  V[1] = add2(ax[0][1], ah[0][1]);
        V[2] = add2(ax[1][0], ah[1][0]);  V[3] = add2(ax[1][1], ah[1][1]);
        V[4] = ax[2][0];  V[5] = ax[2][1];
        V[6] = ah[2][0];  V[7] = ah[2][1];

        if (kg == 2) {
#pragma unroll
            for (int q = 0; q < 8; ++q) bufA[q * 128 + t7] = V[q];
        }
        if (kg == 3) {
#pragma unroll
            for (int q = 0; q < 8; ++q) bufB[q * 128 + t7] = V[q];
        }
        __syncthreads();   // all loops done; wave-1 partials visible

        // prefetch next step's input tile (independent of h) during reduction
        if (t + 1 < NS) {
            const float* ip = inbase + (size_t)(t + 1) * KIN * NB + bb * 32;
            for (int e = tid; e < KIN * 32; e += NTHR)
                sIn[e] = __ldcg(ip + (size_t)(e >> 5) * NB + (e & 31));
        }

        if (kg == 0) {
#pragma unroll
            for (int q = 0; q < 8; ++q) V[q] = add2(V[q], bufA[q * 128 + t7]);
        }
        if (kg == 1) {
#pragma unroll
            for (int q = 0; q < 8; ++q) V[q] = add2(V[q], bufB[q * 128 + t7]);
        }
        __syncthreads();
        if (kg == 1) {
#pragma unroll
            for (int q = 0; q < 8; ++q) bufA[q * 128 + t7] = V[q];
        }
        __syncthreads();

        if (kg == 0) {  // final reduce + GRU update + store
#pragma unroll
            for (int q = 0; q < 8; ++q) V[q] = add2(V[q], bufA[q * 128 + t7]);

            const int jg   = jb * 16 + j;            // global hidden index
            const int bcol = bb * 32 + (bq << 2);    // global batch index
            float hprev[4] = {0.f, 0.f, 0.f, 0.f};
            if (t > 0) {
                float4 hv = *reinterpret_cast<const float4*>(sH + jg * 32 + (bq << 2));
                hprev[0] = hv.x; hprev[1] = hv.y; hprev[2] = hv.z; hprev[3] = hv.w;
            }
            float o[4];
#pragma unroll
            for (int p = 0; p < 2; ++p) {
                float2 s0 = u2f(V[0 + p]);   // xr+hr
                float2 s1 = u2f(V[2 + p]);   // xz+hz
                float2 xn = u2f(V[4 + p]);
                float2 hn = u2f(V[6 + p]);
#pragma unroll
                for (int l = 0; l < 2; ++l) {
                    float vs0 = (l ? s0.y : s0.x) + brz0;
                    float vs1 = (l ? s1.y : s1.x) + brz1;
                    float vxn = (l ? xn.y : xn.x) + bni;
                    float vhn = (l ? hn.y : hn.x) + bnh;
                    float rr = sigm(vs0);
                    float zz = sigm(vs1);
                    float nn = tanhf(vxn + rr * vhn);   // b_hh_n inside r*(.)
                    o[p * 2 + l] = (1.0f - zz) * nn + zz * hprev[p * 2 + l];
                }
            }
            float4 ov = make_float4(o[0], o[1], o[2], o[3]);
            *reinterpret_cast<float4*>(g_hbuf + (t & 1) * (NH * NB) + jg * NB + bcol) = ov;
            if (LAYER == 0)
                *reinterpret_cast<float4*>(g_h1 + ((size_t)t * NH + jg) * NB + bcol) = ov;
            if (LAYER == 1 && t == NS - 1)
                *reinterpret_cast<float4*>(g_final + jg * NB + bcol) = ov;
        }

        if (t < NS - 1) grid_barrier((unsigned)(t + 1));
    }

    if (LAYER == 1) {
        // ---- epilogue: projection + forecast (all CTAs join the barriers) ----
        grid_barrier(600u);                       // g_final complete, visible
        {
            int row = blockIdx.x;                 // 128 rows = 128 CTAs
            float* wrow = reinterpret_cast<float*>(bufA);    // reuse 1 KB
            for (int k = tid; k < NH; k += NTHR) wrow[k] = Wp[row * NH + k];
            __syncthreads();
            if (tid < NB) {
                float acc = bp[row];
#pragma unroll 8
                for (int k = 0; k < NH; ++k)
                    acc += wrow[k] * __ldcg(g_final + k * NB + tid);
                g_s[row * NB + tid] = acc;
            }
        }
        grid_barrier(601u);                       // g_s complete, visible
        if (blockIdx.x < 16) {
            int gid = blockIdx.x * NTHR + tid;    // 0..8191
            int b = gid >> 5, d = gid & 31;
            float a_l = sigm(rld[d]) * 0.15f + 0.85f;
            float a_t = sigm(rtd[d]) * 0.25f + 0.70f;
            float gg  = sigm(rg[d])  * 0.20f + 0.80f;
            float cs = cosf(om[d]), sn = sinf(om[d]);
            float r00 = gg * cs, r01 = -gg * sn, r10 = gg * sn, r11 = gg * cs;
            float C0 = C[d * 4 + 0], C1 = C[d * 4 + 1];
            float C2 = C[d * 4 + 2], C3 = C[d * 4 + 3];
            float s0 = __ldcg(g_s + (d * 4 + 0) * NB + b);
            float s1 = __ldcg(g_s + (d * 4 + 1) * NB + b);
            float s2 = __ldcg(g_s + (d * 4 + 2) * NB + b);
            float s3 = __ldcg(g_s + (d * 4 + 3) * NB + b);
            float* ob = out + (size_t)b * 96 * 32 + d;
#pragma unroll 4
            for (int tt = 0; tt < 96; ++tt) {
                float ns0 = s0 * a_l;
                float ns1 = s1 * a_t;
                float ns2 = s2 * r00 + s3 * r10;
                float ns3 = s2 * r01 + s3 * r11;
                ob[tt * 32] = C0 * ns0 + C1 * ns1 + C2 * ns2 + C3 * ns3;
                s0 = ns0; s1 = ns1; s2 = ns2; s3 = ns3;
            }
        }
    }
}

// ---------------- launch ------------------------------------------------------
extern "C" void kernel_launch(void* const* d_in, const int* in_sizes, int n_in,
                              void* d_out, int out_size)
{
    const float* x    = (const float*)d_in[0];
    const float* Wih0 = (const float*)d_in[1];
    const float* Whh0 = (const float*)d_in[2];
    const float* bih0 = (const float*)d_in[3];
    const float* bhh0 = (const float*)d_in[4];
    const float* Wih1 = (const float*)d_in[5];
    const float* Whh1 = (const float*)d_in[6];
    const float* bih1 = (const float*)d_in[7];
    const float* bhh1 = (const float*)d_in[8];
    const float* Wp   = (const float*)d_in[9];
    const float* bp   = (const float*)d_in[10];
    const float* C    = (const float*)d_in[11];
    const float* rld  = (const float*)d_in[12];
    const float* rtd  = (const float*)d_in[13];
    const float* rg   = (const float*)d_in[14];
    const float* om   = (const float*)d_in[15];
    float* out = (float*)d_out;

    // smem: Whh dup'd (8B) + Wih (4B) + in tile + h tile + 16KB reduction buf
    const int smem0 = NH * 48 * 8 + NIN * 48 * 4 + NIN * 32 * 4 + NH * 32 * 4 + 16384; // 157,696
    const int smem1 = NH * 48 * 8 + NH  * 48 * 4 + NH  * 32 * 4 + NH * 32 * 4 + 16384; // 229,376
    cudaFuncSetAttribute(gru_scan<0>, cudaFuncAttributeMaxDynamicSharedMemorySize, smem0);
    cudaFuncSetAttribute(gru_scan<1>, cudaFuncAttributeMaxDynamicSharedMemorySize, smem1);

    gru_scan<0><<<NCTA, NTHR, smem0>>>(Wih0, Whh0, bih0, bhh0,
                                       nullptr, nullptr, nullptr,
                                       nullptr, nullptr, nullptr, nullptr,
                                       x, nullptr);
    gru_scan<1><<<NCTA, NTHR, smem1>>>(Wih1, Whh1, bih1, bhh1,
                                       Wp, bp, C, rld, rtd, rg, om,
                                       nullptr, out);
}

// round 9
// speedup vs baseline: 1.4954x; 1.2605x over previous
#include <cuda_runtime.h>
#include <cstdint>
#include <cstddef>

typedef unsigned long long ull;

#define NB   256
#define NH   256
#define NS   512
#define NIN  32
#define NCTA 128   // 16 hidden-blocks x 8 batch-blocks
#define NTHR 1024  // 8-way K split x 128 (16j x 8bq)

// ---------------- static device scratch --------------------------------------
__device__ float g_xT[(size_t)NS * NIN * NB];          // x transposed [t][i][b]
__device__ float g_h1[(size_t)NS * NH * NB];           // layer-0 h [t][k][b]
__device__ float g_xp[(size_t)NS * 3 * NH * NB];       // input proj [t][grow][b] (403MB)
__device__ float g_hbuf[2 * NH * NB];                  // double-buffered h [k][b]
__device__ float g_final[NH * NB];
__device__ float g_s[128 * NB];                        // [row][b]
__device__ unsigned g_cnt8[8 * 32];                    // per-batch-group barrier counters
__device__ volatile unsigned g_gen8[8 * 32];
__device__ unsigned g_cntG;                            // global barrier (epilogue only)
__device__ volatile unsigned g_genG;

// ---------------- helpers ----------------------------------------------------
__device__ __forceinline__ ull pack2(float w) {
    ull r; unsigned u = __float_as_uint(w);
    asm("mov.b64 %0, {%1, %1};" : "=l"(r) : "r"(u));
    return r;
}
__device__ __forceinline__ void fma2(ull& acc, ull a, ull b) {
    asm("fma.rn.f32x2 %0, %1, %2, %0;" : "+l"(acc) : "l"(a), "l"(b));
}
__device__ __forceinline__ ull add2(ull a, ull b) {
    ull d; asm("add.rn.f32x2 %0, %1, %2;" : "=l"(d) : "l"(a), "l"(b));
    return d;
}
__device__ __forceinline__ float2 u2f(ull v) {
    float2 f;
    f.x = __uint_as_float((unsigned)(v & 0xffffffffull));
    f.y = __uint_as_float((unsigned)(v >> 32));
    return f;
}
__device__ __forceinline__ float sigm(float x) { return 1.0f / (1.0f + expf(-x)); }

// cp.async.cg: L1-bypassing 16B async copy (L2-coherent -- required for h exchange)
__device__ __forceinline__ void cpa16(uint32_t saddr, const void* gaddr) {
    asm volatile("cp.async.cg.shared.global [%0], [%1], 16;" :: "r"(saddr), "l"(gaddr));
}
__device__ __forceinline__ void cpa_wait_all() {
    asm volatile("cp.async.wait_all;" ::: "memory");
}
__device__ __forceinline__ uint32_t s2u(const void* p) {
    return (uint32_t)__cvta_generic_to_shared(p);
}

// ---------------- barriers ---------------------------------------------------
// Per-batch-group barrier: only the 16 CTAs sharing a batch block sync.
// Equality-compared targets; release pre-resets the counter -> no host reset.
__device__ __forceinline__ void bb_barrier(int bb, unsigned target) {
    __threadfence();
    __syncthreads();
    if (threadIdx.x == 0) {
        unsigned* cnt = &g_cnt8[bb * 32];
        volatile unsigned* gen = &g_gen8[bb * 32];
        unsigned prev = atomicAdd(cnt, 1u);
        if (prev == 15u) {
            atomicExch(cnt, 0u);
            __threadfence();
            *gen = target;
        } else {
            while (*gen != target) { __nanosleep(40); }
            __threadfence();
        }
    }
    __syncthreads();
}
__device__ __forceinline__ void global_barrier(unsigned target) {
    __threadfence();
    __syncthreads();
    if (threadIdx.x == 0) {
        unsigned prev = atomicAdd(&g_cntG, 1u);
        if (prev == (unsigned)(NCTA - 1)) {
            atomicExch(&g_cntG, 0u);
            __threadfence();
            g_genG = target;
        } else {
            while (g_genG != target) { __nanosleep(40); }
            __threadfence();
        }
    }
    __syncthreads();
}

// ---------------- x transpose: [b][t][i] -> [t][i][b] ------------------------
__global__ void transpose_x(const float* __restrict__ x) {
    __shared__ float tile[32][33];
    int t    = blockIdx.x;
    int lane = threadIdx.x & 31;
    int grp  = threadIdx.x >> 5;
    for (int bc = 0; bc < NB; bc += 32) {
#pragma unroll
        for (int q = 0; q < 4; ++q) {
            int bsub = q * 8 + grp;
            tile[bsub][lane] = x[((size_t)(bc + bsub) * NS + t) * NIN + lane];
        }
        __syncthreads();
#pragma unroll
        for (int q = 0; q < 4; ++q) {
            int ii = q * 8 + grp;
            g_xT[((size_t)t * NIN + ii) * NB + bc + lane] = tile[lane][ii];
        }
        __syncthreads();
    }
}

// ---------------- xp GEMM: xp[t][grow][b] = sum_k W[grow][k] * src[t][k][b] --
// t-parallel pre-pass; tile 128 grow x 128 b, k-chunks of 32, f32x2 math.
template <int WHICH>   // 0: src=g_xT, K=32 ; 1: src=g_h1, K=256
__global__ void __launch_bounds__(256)
xp_gemm(const float* __restrict__ W)
{
    constexpr int K = WHICH ? NH : NIN;
    constexpr int NCHUNK = K / 32;
    __shared__ float sA[32][132];   // [k][grow] transposed, padded
    __shared__ float sB[32][128];   // [k][b]
    const float* src = WHICH ? g_h1 : g_xT;

    const int t  = blockIdx.y;
    const int gt = blockIdx.x >> 1;        // 0..5
    const int bt = blockIdx.x & 1;         // 0..1
    const int tid = threadIdx.x;
    const int ty = tid >> 4, tx = tid & 15;

    ull acc[8][4];
#pragma unroll
    for (int i = 0; i < 8; ++i)
#pragma unroll
        for (int p = 0; p < 4; ++p) acc[i][p] = 0ull;

    for (int ck = 0; ck < NCHUNK; ++ck) {
        float4 av[4];
#pragma unroll
        for (int q = 0; q < 4; ++q) {        // A loads overlap prev compute
            int c = tid * 4 + q, r = c >> 3, c4 = c & 7;
            av[q] = *reinterpret_cast<const float4*>(
                W + (size_t)(gt * 128 + r) * K + ck * 32 + c4 * 4);
        }
        __syncthreads();                     // prev compute reads done
#pragma unroll
        for (int q = 0; q < 4; ++q) {        // B direct to smem (L2-resident)
            int c = tid * 4 + q, k = c >> 5, col = (c & 31) * 4;
            cpa16(s2u(&sB[k][col]),
                  src + (size_t)t * K * NB + (size_t)(ck * 32 + k) * NB + bt * 128 + col);
        }
#pragma unroll
        for (int q = 0; q < 4; ++q) {        // A transposed into smem
            int c = tid * 4 + q, r = c >> 3, c4 = c & 7;
            sA[c4 * 4 + 0][r] = av[q].x;
            sA[c4 * 4 + 1][r] = av[q].y;
            sA[c4 * 4 + 2][r] = av[q].z;
            sA[c4 * 4 + 3][r] = av[q].w;
        }
        cpa_wait_all();
        __syncthreads();
#pragma unroll 4
        for (int k = 0; k < 32; ++k) {
            float4 a0 = *reinterpret_cast<const float4*>(&sA[k][ty * 8]);
            float4 a1 = *reinterpret_cast<const float4*>(&sA[k][ty * 8 + 4]);
            ulonglong2 b0 = *reinterpret_cast<const ulonglong2*>(&sB[k][tx * 8]);
            ulonglong2 b1 = *reinterpret_cast<const ulonglong2*>(&sB[k][tx * 8 + 4]);
            float af[8] = {a0.x, a0.y, a0.z, a0.w, a1.x, a1.y, a1.z, a1.w};
#pragma unroll
            for (int i = 0; i < 8; ++i) {
                ull w2 = pack2(af[i]);
                fma2(acc[i][0], w2, b0.x);
                fma2(acc[i][1], w2, b0.y);
                fma2(acc[i][2], w2, b1.x);
                fma2(acc[i][3], w2, b1.y);
            }
        }
    }
    float* outp = g_xp + (size_t)t * 3 * NH * NB
                + (size_t)(gt * 128 + ty * 8) * NB + bt * 128 + tx * 8;
#pragma unroll
    for (int i = 0; i < 8; ++i) {
        ulonglong2 s0; s0.x = acc[i][0]; s0.y = acc[i][1];
        ulonglong2 s1; s1.x = acc[i][2]; s1.y = acc[i][3];
        *reinterpret_cast<ulonglong2*>(outp + (size_t)i * NB)     = s0;
        *reinterpret_cast<ulonglong2*>(outp + (size_t)i * NB + 4) = s1;
    }
}

// ---------------- persistent recurrent-only GRU scan -------------------------
// 1024 thr: kg = tid>>7 (8-way K split, 32 k each), 128 = 16j x 8bq (4 b each).
// Inner iter: LDS.128 (wr,wz dup pairs) + LDS.64 (wn) + LDS.128 (h) + 6 FFMA2.
// xp pre-pass means r/z x-parts arrive pre-summed; accums: 6 ull per thread.
// smem (bytes): sWrz 0..65536, sWn ..98304, sH ..131072, sXp ..137216, bufs ..180224
template <int LAYER>
__global__ void __launch_bounds__(NTHR, 1)
gru_scan(const float* __restrict__ Whh,
         const float* __restrict__ bih, const float* __restrict__ bhh,
         const float* __restrict__ Wp,  const float* __restrict__ bp,
         const float* __restrict__ C,
         const float* __restrict__ rld, const float* __restrict__ rtd,
         const float* __restrict__ rg,  const float* __restrict__ om,
         float* __restrict__ out)
{
    extern __shared__ __align__(16) char smraw[];
    ull*   sWrz = reinterpret_cast<ull*>(smraw);             // [256][16][2]
    ull*   sWn  = reinterpret_cast<ull*>(smraw + 65536);     // [256][16]
    float* sH   = reinterpret_cast<float*>(smraw + 98304);   // [256][32]
    float* sXp  = reinterpret_cast<float*>(smraw + 131072);  // [3][16][32]
    ull*   bufs = reinterpret_cast<ull*>(smraw + 137216);    // [7][128][6]

    const int tid = threadIdx.x;
    const int kg  = tid >> 7;              // 0..7
    const int t7  = tid & 127;
    const int j   = t7 >> 3;               // 0..15
    const int bq  = t7 & 7;                // 0..7
    const int jb  = blockIdx.x & 15;
    const int bb  = blockIdx.x >> 4;
    const int jg  = jb * 16 + j;
    const int bcol = bb * 32 + (bq << 2);

    // weights: (r,z) rows as duplicated-pair LDS.128 units; n rows separate
    for (int e = tid; e < NH * 16; e += NTHR) {
        int k = e >> 4, jj = e & 15;
        int rr = jb * 16 + jj;
        sWrz[e * 2 + 0] = pack2(Whh[(size_t)rr * NH + k]);
        sWrz[e * 2 + 1] = pack2(Whh[(size_t)(NH + rr) * NH + k]);
        sWn[e]          = pack2(Whh[(size_t)(2 * NH + rr) * NH + k]);
    }
    float brz0 = bih[jg] + bhh[jg];
    float brz1 = bih[NH + jg] + bhh[NH + jg];
    float bni  = bih[2 * NH + jg];
    float bnh  = bhh[2 * NH + jg];
    __syncthreads();

    const float* xpbase = g_xp + (size_t)(jb * 16) * NB + bb * 32;

    for (int t = 0; t < NS; ++t) {
        // phase A: async fills (xp tile by kg7; h tile by everyone, t>0)
        if (kg == 7) {
            const float* xpt = g_xp + (size_t)t * 3 * NH * NB;
#pragma unroll
            for (int q = 0; q < 3; ++q) {
                int c = t7 * 3 + q;          // 0..383 16B chunks
                int row = c >> 3, col = c & 7;
                int g = row >> 4, jj = row & 15;
                cpa16(s2u(&sXp[row * 32 + col * 4]),
                      xpt + (size_t)(g * NH + jb * 16 + jj) * NB + bb * 32 + col * 4);
            }
        }
        if (t > 0) {
            const float* hp = g_hbuf + ((t - 1) & 1) * (NH * NB) + bb * 32;
            int fidx = tid * 8;
            int k = fidx >> 5, off = fidx & 31;
            cpa16(s2u(&sH[fidx]),     hp + (size_t)k * NB + off);
            cpa16(s2u(&sH[fidx + 4]), hp + (size_t)k * NB + off + 4);
        }
        cpa_wait_all();
        __syncthreads();

        // phase B: recurrent accumulation (32 k per thread)
        ull ar0 = 0, ar1 = 0, az0 = 0, az1 = 0, an0 = 0, an1 = 0;
        if (t > 0) {
            const int kb = kg * 32;
            const ull* wrzp = sWrz + (size_t)kb * 32 + j * 2;
            const ull* wnp  = sWn + (size_t)kb * 16 + j;
            const float* hp = sH + (kb << 5) + (bq << 2);
#pragma unroll 8
            for (int kk = 0; kk < 32; ++kk) {
                ulonglong2 wv = *reinterpret_cast<const ulonglong2*>(wrzp + kk * 32);
                ull wn2 = wnp[kk * 16];
                ulonglong2 hv = *reinterpret_cast<const ulonglong2*>(hp + (kk << 5));
                fma2(ar0, wv.x, hv.x); fma2(ar1, wv.x, hv.y);
                fma2(az0, wv.y, hv.x); fma2(az1, wv.y, hv.y);
                fma2(an0, wn2,  hv.x); fma2(an1, wn2,  hv.y);
            }
        }

        // phase C: publish (kg 1..7)
        if (kg > 0) {
            ull* wp = bufs + ((size_t)(kg - 1) * 128 + t7) * 6;
            ulonglong2 p0; p0.x = ar0; p0.y = ar1;
            ulonglong2 p1; p1.x = az0; p1.y = az1;
            ulonglong2 p2; p2.x = an0; p2.y = an1;
            *reinterpret_cast<ulonglong2*>(wp)     = p0;
            *reinterpret_cast<ulonglong2*>(wp + 2) = p1;
            *reinterpret_cast<ulonglong2*>(wp + 4) = p2;
        }
        __syncthreads();

        // phase D: kg0 reduces + GRU update + h store
        if (kg == 0) {
#pragma unroll
            for (int gs = 0; gs < 7; ++gs) {
                const ull* rp = bufs + ((size_t)gs * 128 + t7) * 6;
                ulonglong2 r0 = *reinterpret_cast<const ulonglong2*>(rp);
                ulonglong2 r1 = *reinterpret_cast<const ulonglong2*>(rp + 2);
                ulonglong2 r2 = *reinterpret_cast<const ulonglong2*>(rp + 4);
                ar0 = add2(ar0, r0.x); ar1 = add2(ar1, r0.y);
                az0 = add2(az0, r1.x); az1 = add2(az1, r1.y);
                an0 = add2(an0, r2.x); an1 = add2(an1, r2.y);
            }
            ulonglong2 xr = *reinterpret_cast<const ulonglong2*>(&sXp[(0 * 16 + j) * 32 + (bq << 2)]);
            ulonglong2 xz = *reinterpret_cast<const ulonglong2*>(&sXp[(1 * 16 + j) * 32 + (bq << 2)]);
            ulonglong2 xn = *reinterpret_cast<const ulonglong2*>(&sXp[(2 * 16 + j) * 32 + (bq << 2)]);
            float hprev[4] = {0.f, 0.f, 0.f, 0.f};
            if (t > 0) {
                float4 hv = *reinterpret_cast<const float4*>(&sH[jg * 32 + (bq << 2)]);
                hprev[0] = hv.x; hprev[1] = hv.y; hprev[2] = hv.z; hprev[3] = hv.w;
            }
            ull arr[2] = {ar0, ar1}, azz[2] = {az0, az1}, ann[2] = {an0, an1};
            ull xrr[2] = {xr.x, xr.y}, xzz[2] = {xz.x, xz.y}, xnn[2] = {xn.x, xn.y};
            float o[4];
#pragma unroll
            for (int p = 0; p < 2; ++p) {
                float2 hr = u2f(arr[p]), hz = u2f(azz[p]), hn = u2f(ann[p]);
                float2 fr = u2f(xrr[p]), fz = u2f(xzz[p]), fn = u2f(xnn[p]);
#pragma unroll
                for (int l = 0; l < 2; ++l) {
                    float vr = (l ? hr.y : hr.x) + (l ? fr.y : fr.x) + brz0;
                    float vz = (l ? hz.y : hz.x) + (l ? fz.y : fz.x) + brz1;
                    float vhn = (l ? hn.y : hn.x) + bnh;
                    float vxn = (l ? fn.y : fn.x) + bni;
                    float rr = sigm(vr);
                    float zz = sigm(vz);
                    float nn = tanhf(vxn + rr * vhn);
                    o[p * 2 + l] = (1.0f - zz) * nn + zz * hprev[p * 2 + l];
                }
            }
            float4 ov = make_float4(o[0], o[1], o[2], o[3]);
            *reinterpret_cast<float4*>(g_hbuf + (t & 1) * (NH * NB) + (size_t)jg * NB + bcol) = ov;
            if (LAYER == 0)
                *reinterpret_cast<float4*>(g_h1 + ((size_t)t * NH + jg) * NB + bcol) = ov;
            if (LAYER == 1 && t == NS - 1)
                *reinterpret_cast<float4*>(g_final + (size_t)jg * NB + bcol) = ov;
        }

        if (t < NS - 1) bb_barrier(bb, (unsigned)(t + 1));
    }

    if (LAYER == 1) {
        // ---- epilogue: projection + forecast ----
        global_barrier(600u);
        {
            int row = blockIdx.x;
            float* wrow = reinterpret_cast<float*>(smraw);   // weights dead now
            for (int k = tid; k < NH; k += NTHR) wrow[k] = Wp[(size_t)row * NH + k];
            __syncthreads();
            if (tid < NB) {
                float acc = bp[row];
#pragma unroll 8
                for (int k = 0; k < NH; ++k)
                    acc += wrow[k] * __ldcg(g_final + (size_t)k * NB + tid);
                g_s[(size_t)row * NB + tid] = acc;
            }
        }
        global_barrier(601u);
        if (blockIdx.x < 8) {
            int gid = blockIdx.x * NTHR + tid;   // 0..8191
            int b = gid >> 5, d = gid & 31;
            float a_l = sigm(rld[d]) * 0.15f + 0.85f;
            float a_t = sigm(rtd[d]) * 0.25f + 0.70f;
            float gg  = sigm(rg[d])  * 0.20f + 0.80f;
            float cs = cosf(om[d]), sn = sinf(om[d]);
            float r00 = gg * cs, r01 = -gg * sn, r10 = gg * sn, r11 = gg * cs;
            float C0 = C[d * 4 + 0], C1 = C[d * 4 + 1];
            float C2 = C[d * 4 + 2], C3 = C[d * 4 + 3];
            float s0 = __ldcg(g_s + (size_t)(d * 4 + 0) * NB + b);
            float s1 = __ldcg(g_s + (size_t)(d * 4 + 1) * NB + b);
            float s2 = __ldcg(g_s + (size_t)(d * 4 + 2) * NB + b);
            float s3 = __ldcg(g_s + (size_t)(d * 4 + 3) * NB + b);
            float* ob = out + (size_t)b * 96 * 32 + d;
#pragma unroll 4
            for (int tt = 0; tt < 96; ++tt) {
                float ns0 = s0 * a_l;
                float ns1 = s1 * a_t;
                float ns2 = s2 * r00 + s3 * r10;
                float ns3 = s2 * r01 + s3 * r11;
                ob[tt * 32] = C0 * ns0 + C1 * ns1 + C2 * ns2 + C3 * ns3;
                s0 = ns0; s1 = ns1; s2 = ns2; s3 = ns3;
            }
        }
    }
}

// ---------------- launch ------------------------------------------------------
extern "C" void kernel_launch(void* const* d_in, const int* in_sizes, int n_in,
                              void* d_out, int out_size)
{
    const float* x    = (const float*)d_in[0];
    const float* Wih0 = (const float*)d_in[1];
    const float* Whh0 = (const float*)d_in[2];
    const float* bih0 = (const float*)d_in[3];
    const float* bhh0 = (const float*)d_in[4];
    const float* Wih1 = (const float*)d_in[5];
    const float* Whh1 = (const float*)d_in[6];
    const float* bih1 = (const float*)d_in[7];
    const float* bhh1 = (const float*)d_in[8];
    const float* Wp   = (const float*)d_in[9];
    const float* bp   = (const float*)d_in[10];
    const float* C    = (const float*)d_in[11];
    const float* rld  = (const float*)d_in[12];
    const float* rtd  = (const float*)d_in[13];
    const float* rg   = (const float*)d_in[14];
    const float* om   = (const float*)d_in[15];
    float* out = (float*)d_out;

    const int smem = 180224;   // sWrz 64K + sWn 32K + sH 32K + sXp 6K + bufs 42K
    cudaFuncSetAttribute(gru_scan<0>, cudaFuncAttributeMaxDynamicSharedMemorySize, smem);
    cudaFuncSetAttribute(gru_scan<1>, cudaFuncAttributeMaxDynamicSharedMemorySize, smem);

    dim3 gg(12, NS);
    transpose_x<<<NS, 256>>>(x);
    xp_gemm<0><<<gg, 256>>>(Wih0);
    gru_scan<0><<<NCTA, NTHR, smem>>>(Whh0, bih0, bhh0,
                                      nullptr, nullptr, nullptr,
                                      nullptr, nullptr, nullptr, nullptr, nullptr);
    xp_gemm<1><<<gg, 256>>>(Wih1);
    gru_scan<1><<<NCTA, NTHR, smem>>>(Whh1, bih1, bhh1,
                                      Wp, bp, C, rld, rtd, rg, om, out);
}